// round 14
// baseline (speedup 1.0000x reference)
#include <cuda_runtime.h>

#define RB 64
#define CB 64
#define NROWS 8192
#define TCOLS 8192
#define T4 (TCOLS / 4)         // 2048 float4 per row
#define NCHUNK 8               // 1024 columns (256 float4) per chunk
#define NSPLIT 2               // row halves per row-block

__device__ int   g_row_start[RB + 1];
__device__ int   g_col_start[CB + 1];
// zero at module load; k_mlp re-zeroes after reading so graph replays are clean
__device__ float g_sum[RB * CB];

__device__ __forceinline__ void pdl_trigger() {
    asm volatile("griddepcontrol.launch_dependents;" ::: "memory");
}
__device__ __forceinline__ void pdl_wait() {
    asm volatile("griddepcontrol.wait;" ::: "memory");
}

// ---------------------------------------------------------------------------
// Kernel 1 (main): grid (NCHUNK+1, RB, NSPLIT).
//   chunk < NCHUNK  : sum role. Cooperative 2-round bounds search, unroll-4
//                     LDG.128 stream, shared acc -> g_sum float atomics.
//   chunk == NCHUNK : bounds-output role (rb==0: rows, rb==1: cols), writes
//                     cumsums to out and g_*_start. Hidden under the stream.
// Every block ends with fence + griddepcontrol.launch_dependents so the
// PDL-launched k_mlp sees all g_sum/g_*_start writes after its wait.
//
// Output layout:
//   out[0..4095]      propensity (written by k_mlp)
//   out[4096..4160]   row_cumsum (65, float values)
//   out[4161..4225]   col_cumsum (65, float values)
// ---------------------------------------------------------------------------
__global__ __launch_bounds__(256) void k_sum(const float* __restrict__ X,
                                             const int* __restrict__ row_ids,
                                             const int* __restrict__ col_ids,
                                             float* __restrict__ out) {
    int tid = threadIdx.x;
    int chunk = blockIdx.x;            // 0..NCHUNK (last = bounds role)
    int rb    = blockIdx.y;            // 0..RB-1
    int half  = blockIdx.z;            // 0..NSPLIT-1

    if (chunk == NCHUNK) {
        // -------- bounds-output role --------
        if (rb > 1 || half != 0) { pdl_trigger(); return; }
        const int* __restrict__ ids = (rb == 0) ? row_ids : col_ids;
        int* __restrict__ gstart = (rb == 0) ? g_row_start : g_col_start;
        float* __restrict__ obase = out + RB * CB + rb * 65;
        if (tid == 0) {
            gstart[0] = 0;       obase[0]  = 0.f;
            gstart[RB] = NROWS;  obase[RB] = (float)NROWS;
        }
        const int4* __restrict__ p = (const int4*)ids;
        for (int i = tid; i < NROWS / 4; i += 256) {
            int4 v = p[i];
            int j = 4 * i;
            if (j > 0) {
                int prev = ids[j - 1];
                if (v.x != prev) { gstart[v.x] = j;     obase[v.x] = (float)j; }
            }
            if (v.y != v.x) { gstart[v.y] = j + 1; obase[v.y] = (float)(j + 1); }
            if (v.z != v.y) { gstart[v.z] = j + 2; obase[v.z] = (float)(j + 2); }
            if (v.w != v.z) { gstart[v.w] = j + 3; obase[v.w] = (float)(j + 3); }
        }
        __threadfence();
        pdl_trigger();
        return;
    }

    // -------- sum role: cooperative 2-round lower_bound for rb and rb+1 ----
    __shared__ int sprobe[256];
    __shared__ int sbr[2];     // coarse bracket index t for target rb / rb+1
    __shared__ int sres[2];    // refined r0 / r1

    sprobe[tid] = row_ids[tid * 32];           // one parallel gather round
    if (tid < 2) sbr[tid] = -1;
    __syncthreads();
    // sorted => predicate (sprobe[t] < target) is a true-prefix; find boundary
    {
        int v = sprobe[tid];
        int vn = (tid < 255) ? sprobe[tid + 1] : 0x7fffffff;
        if (v < rb && vn >= rb)         sbr[0] = tid;
        if (v < rb + 1 && vn >= rb + 1) sbr[1] = tid;
    }
    __syncthreads();
    if (tid < 64) {                            // warps 0,1: refine each target
        int w = tid >> 5;                      // 0 -> rb, 1 -> rb+1
        int lane = tid & 31;
        int target = rb + w;
        int t = sbr[w];
        int start = (t < 0) ? 0 : t * 32 + 1;  // lower_bound lies in [start, start+32]
        int pos = start + lane;
        int v = (pos < NROWS) ? row_ids[pos] : 0x7fffffff;
        unsigned m = __ballot_sync(0xffffffffu, v < target);
        if (lane == 0) sres[w] = start + __popc(m);
    }
    __syncthreads();
    int r0 = sres[0];
    int r1 = sres[1];

    int len = r1 - r0;
    int h0 = r0 + (len * half) / NSPLIT;
    int h1 = r0 + (len * (half + 1)) / NSPLIT;

    int c4 = chunk * 256 + tid;                  // float4 column index
    const float4* __restrict__ Xp = (const float4*)X;

    float ax = 0.f, ay = 0.f, az = 0.f, aw = 0.f;
    int base = h0 * T4 + c4;
    int n = h0;
    for (; n + 4 <= h1; n += 4, base += 4 * T4) {
        float4 v0 = Xp[base];
        float4 v1 = Xp[base + T4];
        float4 v2 = Xp[base + 2 * T4];
        float4 v3 = Xp[base + 3 * T4];
        ax += (v0.x + v1.x) + (v2.x + v3.x);
        ay += (v0.y + v1.y) + (v2.y + v3.y);
        az += (v0.z + v1.z) + (v2.z + v3.z);
        aw += (v0.w + v1.w) + (v2.w + v3.w);
    }
    for (; n < h1; n++, base += T4) {
        float4 v = Xp[base];
        ax += v.x; ay += v.y; az += v.z; aw += v.w;
    }

    __shared__ float sacc[CB];
    if (tid < CB) sacc[tid] = 0.f;
    __syncthreads();

    int t4i = c4 * 4;
    int cb0 = col_ids[t4i];
    int cb3 = col_ids[t4i + 3];
    if (cb0 == cb3) {
        atomicAdd(&sacc[cb0], ax + ay + az + aw);
    } else {
        int cb1 = col_ids[t4i + 1];
        int cb2 = col_ids[t4i + 2];
        atomicAdd(&sacc[cb0], ax);
        atomicAdd(&sacc[cb1], ay);
        atomicAdd(&sacc[cb2], az);
        atomicAdd(&sacc[cb3], aw);
    }
    __syncthreads();
    if (tid < CB) atomicAdd(&g_sum[rb * CB + tid], sacc[tid]);
    __threadfence();
    pdl_trigger();
}

// ---------------------------------------------------------------------------
// Kernel 2 (PDL dependent): waits for all k_sum blocks, then block mean ->
// 1->3->3->1 relu MLP -> sigmoid. Re-zeroes g_sum for clean graph replays.
// ---------------------------------------------------------------------------
__global__ void k_mlp(const float* __restrict__ W1, const float* __restrict__ b1,
                      const float* __restrict__ W2, const float* __restrict__ b2,
                      const float* __restrict__ W3, const float* __restrict__ b3,
                      float* __restrict__ out) {
    pdl_wait();
    int idx = blockIdx.x * blockDim.x + threadIdx.x;
    if (idx >= RB * CB) return;
    int rb = idx / CB;
    int cb = idx % CB;
    float s = g_sum[idx];
    g_sum[idx] = 0.f;   // reset for next call
    float rcnt = (float)(g_row_start[rb + 1] - g_row_start[rb]);
    float ccnt = (float)(g_col_start[cb + 1] - g_col_start[cb]);
    float x = s / (rcnt * ccnt);

    float h1v[3], h2v[3];
#pragma unroll
    for (int j = 0; j < 3; j++) h1v[j] = fmaxf(x * W1[j] + b1[j], 0.f);
#pragma unroll
    for (int j = 0; j < 3; j++) {
        float v = b2[j];
#pragma unroll
        for (int i = 0; i < 3; i++) v += h1v[i] * W2[i * 3 + j];
        h2v[j] = fmaxf(v, 0.f);
    }
    float o = b3[0];
#pragma unroll
    for (int i = 0; i < 3; i++) o += h2v[i] * W3[i];
    out[idx] = 1.f / (1.f + __expf(-o));
}

extern "C" void kernel_launch(void* const* d_in, const int* in_sizes, int n_in,
                              void* d_out, int out_size) {
    const float* X       = (const float*)d_in[0];
    const int*   row_ids = (const int*)d_in[1];
    const int*   col_ids = (const int*)d_in[2];
    const float* W1      = (const float*)d_in[3];
    const float* b1      = (const float*)d_in[4];
    const float* W2      = (const float*)d_in[5];
    const float* b2      = (const float*)d_in[6];
    const float* W3      = (const float*)d_in[7];
    const float* b3      = (const float*)d_in[8];
    float* out = (float*)d_out;

    k_sum<<<dim3(NCHUNK + 1, RB, NSPLIT), 256>>>(X, row_ids, col_ids, out);

    // PDL launch of the epilogue: its launch latency overlaps k_sum.
    cudaLaunchConfig_t cfg = {};
    cfg.gridDim  = dim3(32, 1, 1);
    cfg.blockDim = dim3(128, 1, 1);
    cfg.dynamicSmemBytes = 0;
    cfg.stream = 0;
    cudaLaunchAttribute attrs[1];
    attrs[0].id = cudaLaunchAttributeProgrammaticStreamSerialization;
    attrs[0].val.programmaticStreamSerializationAllowed = 1;
    cfg.attrs = attrs;
    cfg.numAttrs = 1;
    cudaLaunchKernelEx(&cfg, k_mlp, W1, b1, W2, b2, W3, b3, out);
}